// round 4
// baseline (speedup 1.0000x reference)
#include <cuda_runtime.h>
#include <cuda_fp16.h>
#include <cstdint>

// AWQ INT4 dequant GEMM: C[64, 28672] = A[64, 8192] @ dequant(qweight) + bias
// Harness delivers fp16 tensors as float32 (no fp16 in its dtype map), so:
//   A: f32 [64,8192], qweight: i32 [1024,28672], scales: f32 [64,28672/...],
//   bias: f32 [28672], out: f32 [64,28672].
// Pre-pass converts A/scales/bias to fp16 statics (exact — values are fp16-
// representable), then the fp16 tensor-core pipeline runs unchanged.

#define MDIM 64
#define KDIM 8192
#define NDIM 28672
#define NGROUPS (KDIM / 128)   // 64
#define NTILE 128
#define KB 64
#define NCHUNK (KDIM / KB)     // 128
#define THREADS 256

__device__ half g_A[MDIM * KDIM];          // 1 MB
__device__ half g_scales[NGROUPS * NDIM];  // 3.5 MB
__device__ half g_bias[NDIM];              // 56 KB

__device__ __forceinline__ uint32_t smem_u32(const void* p) {
    return (uint32_t)__cvta_generic_to_shared(p);
}

__global__ void convert_f32_to_f16_kernel(const float* __restrict__ A,
                                          const float* __restrict__ scales,
                                          const float* __restrict__ bias)
{
    const int stride = gridDim.x * blockDim.x;
    int i = blockIdx.x * blockDim.x + threadIdx.x;
    // A: process as float2 -> half2
    for (int j = i; j < MDIM * KDIM / 2; j += stride) {
        float2 v = reinterpret_cast<const float2*>(A)[j];
        reinterpret_cast<half2*>(g_A)[j] = __floats2half2_rn(v.x, v.y);
    }
    for (int j = i; j < NGROUPS * NDIM / 2; j += stride) {
        float2 v = reinterpret_cast<const float2*>(scales)[j];
        reinterpret_cast<half2*>(g_scales)[j] = __floats2half2_rn(v.x, v.y);
    }
    for (int j = i; j < NDIM / 2; j += stride) {
        float2 v = reinterpret_cast<const float2*>(bias)[j];
        reinterpret_cast<half2*>(g_bias)[j] = __floats2half2_rn(v.x, v.y);
    }
}

__global__ __launch_bounds__(THREADS, 2)
void awq_gemm_kernel(const int* __restrict__ qw,
                     float* __restrict__ out)
{
    // Double-buffered staging.
    __shared__ half A_sm[2][64][72];   // 18432 B (72 pad: conflict-free ldmatrix)
    __shared__ int  q_sm[2][8][128];   //  8192 B

    const int tid  = threadIdx.x;
    const int lane = tid & 31;
    const int wid  = tid >> 5;
    const int wn   = wid & 3;          // warp column 0..3 (32 N each)
    const int wm   = wid >> 2;         // warp row    0..1 (32 M each)
    const int gidq = lane >> 2;        // 0..7  (mma group id)
    const int tj   = lane & 3;         // 0..3  (thread-in-group)

    const int n0 = blockIdx.x * NTILE;

    const int ar  = tid >> 2;          // A row 0..63
    const int ac  = tid & 3;           // A 16B-chunk selector
    const int kqr = wid;               // q word-row 0..7
    const int nq4 = lane * 4;          // q column (x4 words)

    float acc[2][4][4];
    #pragma unroll
    for (int i = 0; i < 2; i++)
        #pragma unroll
        for (int j = 0; j < 4; j++)
            #pragma unroll
            for (int k = 0; k < 4; k++) acc[i][j][k] = 0.f;

    half2 s2[4];
    const half2 C1032 = __half2half2(__ushort_as_half((unsigned short)0x6408)); // 1032.0 exact

    auto issue_chunk = [&](int c, int b) {
        const int k0 = c * KB;
        #pragma unroll
        for (int j = 0; j < 2; ++j) {
            const int koff = (ac + 4 * j) * 8;
            const half* src = g_A + ar * KDIM + k0 + koff;
            uint32_t dst = smem_u32(&A_sm[b][ar][koff]);
            asm volatile("cp.async.cg.shared.global [%0], [%1], 16;\n"
                         :: "r"(dst), "l"(src));
        }
        {
            const int* src = qw + (size_t)(k0 / 8 + kqr) * NDIM + n0 + nq4;
            uint32_t dst = smem_u32(&q_sm[b][kqr][nq4]);
            asm volatile("cp.async.cg.shared.global [%0], [%1], 16;\n"
                         :: "r"(dst), "l"(src));
        }
        asm volatile("cp.async.commit_group;\n" ::: "memory");
    };

    issue_chunk(0, 0);

    for (int c = 0; c < NCHUNK; ++c) {
        if (c + 1 < NCHUNK) {
            issue_chunk(c + 1, (c + 1) & 1);
            asm volatile("cp.async.wait_group 1;\n" ::: "memory");
        } else {
            asm volatile("cp.async.wait_group 0;\n" ::: "memory");
        }
        __syncthreads();

        const int b = c & 1;

        // Per-group scales (group = 128 K = 2 chunks)
        if ((c & 1) == 0) {
            const int g = c >> 1;
            #pragma unroll
            for (int nb = 0; nb < 4; ++nb) {
                const int col = n0 + wn * 32 + nb * 8 + gidq;
                s2[nb] = __half2half2(g_scales[g * NDIM + col]);
            }
        }

        #pragma unroll
        for (int s = 0; s < 4; ++s) {
            uint32_t a[2][4];
            #pragma unroll
            for (int mf = 0; mf < 2; ++mf) {
                const int row = wm * 32 + mf * 16 + (lane & 15);
                const int col = s * 16 + ((lane >> 4) << 3);
                uint32_t addr = smem_u32(&A_sm[b][row][col]);
                asm volatile("ldmatrix.sync.aligned.m8n8.x4.shared.b16 {%0,%1,%2,%3}, [%4];\n"
                             : "=r"(a[mf][0]), "=r"(a[mf][1]),
                               "=r"(a[mf][2]), "=r"(a[mf][3])
                             : "r"(addr));
            }
            #pragma unroll
            for (int nb = 0; nb < 4; ++nb) {
                const int ncol = wn * 32 + nb * 8 + gidq;
                // byte tj of word 2s holds k-rows {2tj,2tj+1}; word 2s+1 -> {8+2tj,9+2tj}
                uint32_t w0 = (uint32_t)q_sm[b][2 * s][ncol];
                uint32_t w1 = (uint32_t)q_sm[b][2 * s + 1][ncol];
                uint32_t q0 = w0 >> (tj * 8);
                uint32_t q1 = w1 >> (tj * 8);
                // {1024+nib_lo, 1024+nib_hi} as fp16x2 (exact), isolated masks
                uint32_t v0 = (q0 & 0x0000000Fu) | ((q0 & 0x000000F0u) << 12) | 0x64006400u;
                uint32_t v1 = (q1 & 0x0000000Fu) | ((q1 & 0x000000F0u) << 12) | 0x64006400u;
                half2 h0 = __hmul2(__hsub2(*reinterpret_cast<half2*>(&v0), C1032), s2[nb]);
                half2 h1 = __hmul2(__hsub2(*reinterpret_cast<half2*>(&v1), C1032), s2[nb]);
                uint32_t b0 = reinterpret_cast<uint32_t&>(h0);
                uint32_t b1 = reinterpret_cast<uint32_t&>(h1);
                #pragma unroll
                for (int mf = 0; mf < 2; ++mf) {
                    asm volatile(
                        "mma.sync.aligned.m16n8k16.row.col.f32.f16.f16.f32 "
                        "{%0,%1,%2,%3}, {%4,%5,%6,%7}, {%8,%9}, {%0,%1,%2,%3};\n"
                        : "+f"(acc[mf][nb][0]), "+f"(acc[mf][nb][1]),
                          "+f"(acc[mf][nb][2]), "+f"(acc[mf][nb][3])
                        : "r"(a[mf][0]), "r"(a[mf][1]), "r"(a[mf][2]), "r"(a[mf][3]),
                          "r"(b0), "r"(b1));
                }
            }
        }
        __syncthreads();
    }

    // Epilogue: fp32 acc -> fp16 round, + fp16 bias (reference numerics),
    // then widen to f32 for the output buffer.
    #pragma unroll
    for (int mf = 0; mf < 2; ++mf) {
        #pragma unroll
        for (int nb = 0; nb < 4; ++nb) {
            const int col = n0 + wn * 32 + nb * 8 + 2 * tj;
            const half2 bb = *reinterpret_cast<const half2*>(g_bias + col);
            const int row0 = wm * 32 + mf * 16 + gidq;
            half2 o0 = __hadd2(__floats2half2_rn(acc[mf][nb][0], acc[mf][nb][1]), bb);
            half2 o1 = __hadd2(__floats2half2_rn(acc[mf][nb][2], acc[mf][nb][3]), bb);
            float2 f0 = make_float2(__low2float(o0), __high2float(o0));
            float2 f1 = make_float2(__low2float(o1), __high2float(o1));
            *reinterpret_cast<float2*>(out + (size_t)row0 * NDIM + col)       = f0;
            *reinterpret_cast<float2*>(out + (size_t)(row0 + 8) * NDIM + col) = f1;
        }
    }
}

extern "C" void kernel_launch(void* const* d_in, const int* in_sizes, int n_in,
                              void* d_out, int out_size) {
    // Bind inputs by element count (all four counts are distinct).
    const float* A      = nullptr;
    const int*   qwt    = nullptr;
    const float* scales = nullptr;
    const float* bias   = nullptr;
    for (int i = 0; i < n_in; ++i) {
        switch (in_sizes[i]) {
            case MDIM * KDIM:        A      = (const float*)d_in[i]; break; // 524288
            case (KDIM / 8) * NDIM:  qwt    = (const int*)d_in[i];   break; // 29360128
            case NGROUPS * NDIM:     scales = (const float*)d_in[i]; break; // 1835008
            case NDIM:               bias   = (const float*)d_in[i]; break; // 28672
            default: break;
        }
    }
    float* out = (float*)d_out;

    convert_f32_to_f16_kernel<<<592, 256>>>(A, scales, bias);
    awq_gemm_kernel<<<NDIM / NTILE, THREADS>>>(qwt, out);  // 224 CTAs
}